// round 11
// baseline (speedup 1.0000x reference)
#include <cuda_runtime.h>
#include <cuda_fp16.h>
#include <stdint.h>
#include <math.h>

#define NB   64
#define LSEQ 510
#define DDIM 768
#define L1   128
#define KN   20
#define OUTD 300
#define EPSV 1e-5f

#define NSPAN1 (NB * L1)          // 8192
#define NSPANK (NB * KN)          // 1280
#define NSPANS (NSPAN1 + NSPANK)  // 9472
#define TROWS  32
#define NTILES (NSPANS / TROWS)   // 296 = 2 CTAs x 148 SMs
#define NBLK1T (NSPAN1 / TROWS)   // 256

#define NCHUNK 12                 // K chunks of 64
#define NPADB  320

#define H1_OFF    0
#define SCORE_OFF (NB * L1 * OUTD)
#define HK_OFF    (2 * NB * L1 * OUTD)
#define SK_OFF    (HK_OFF + NB * KN * OUTD)

#define A_CHUNK_BYTES 4096         // 32 rows x 128B (fp16)
#define B_CHUNK_BYTES 40960        // 320 rows x 128B (fp16)

__device__ __align__(16) unsigned char g_Ahi[NTILES * NCHUNK * A_CHUNK_BYTES];
__device__ __align__(16) unsigned char g_Bhi[NCHUNK * B_CHUNK_BYTES];
__device__ float g_scores[NSPANS];
__device__ int   g_mask_mode;

// smem: per stage Ahi 4K | Bhi 40K = 44K; x2 stages; tables; reduction
#define STAGE_BYTES 45056
#define OFF_AHI 0
#define OFF_BHI 4096
#define SM_TAB  (2 * STAGE_BYTES)          // 90112
#define SM_RED  (SM_TAB + 5120)           // 95232
#define SMEM_BYTES (SM_RED + 3584)        // 98816 -> 2 CTAs/SM

static __device__ __forceinline__ uint32_t smem_u32(const void* p) {
    uint32_t a;
    asm("{ .reg .u64 t; cvta.to.shared.u64 t, %1; cvt.u32.u64 %0, t; }" : "=r"(a) : "l"(p));
    return a;
}
static __device__ __forceinline__ void cp16(uint32_t s, const void* g) {
    asm volatile("cp.async.cg.shared.global [%0], [%1], 16;" :: "r"(s), "l"(g) : "memory");
}
static __device__ __forceinline__ void ldsm4(uint32_t* r, uint32_t addr) {
    asm volatile("ldmatrix.sync.aligned.m8n8.x4.shared.b16 {%0,%1,%2,%3}, [%4];"
                 : "=r"(r[0]), "=r"(r[1]), "=r"(r[2]), "=r"(r[3]) : "r"(addr));
}
static __device__ __forceinline__ void ldsm2(uint32_t* r, uint32_t addr) {
    asm volatile("ldmatrix.sync.aligned.m8n8.x2.shared.b16 {%0,%1}, [%2];"
                 : "=r"(r[0]), "=r"(r[1]) : "r"(addr));
}
static __device__ __forceinline__ void mma16816(float* c, const uint32_t* a,
                                                const uint32_t* b) {
    asm volatile(
        "mma.sync.aligned.m16n8k16.row.col.f32.f16.f16.f32 "
        "{%0,%1,%2,%3}, {%4,%5,%6,%7}, {%8,%9}, {%0,%1,%2,%3};"
        : "+f"(c[0]), "+f"(c[1]), "+f"(c[2]), "+f"(c[3])
        : "r"(a[0]), "r"(a[1]), "r"(a[2]), "r"(a[3]), "r"(b[0]), "r"(b[1]));
}
static __device__ __forceinline__ uint32_t swz_addr(uint32_t base, int row, int u) {
    return base + row * 128 + ((u ^ (row & 7)) << 4);
}
static __device__ __forceinline__ bool read_mask(const void* m, int i, int mode) {
    if (mode == 0) return ((const unsigned char*)m)[i] != 0;
    if (mode == 1) return ((const int*)m)[i] != 0;
    return ((const float*)m)[i] != 0.0f;
}

// ---------------------------------------------------------------------------
// prep: blocks [0,3552): 3-warps-per-span pooling, MLP-8 clamped loads;
//       blocks [3552,3672): W -> fp16; block 3672: mask detect.
// ---------------------------------------------------------------------------
#define PREP_SPAN_BLKS (NSPANS * 3 / 8)   // 3552
#define PREP_W_BLKS    120
#define PREP_BLKS      (PREP_SPAN_BLKS + PREP_W_BLKS + 1)

__global__ __launch_bounds__(256)
void prep_kernel(const float* __restrict__ t1, const float* __restrict__ know,
                 const int* __restrict__ s1s, const int* __restrict__ s1e,
                 const int* __restrict__ sks, const int* __restrict__ ske,
                 const float* __restrict__ W,
                 const unsigned char* __restrict__ mask1,
                 const unsigned char* __restrict__ maskk) {
    const int bid = blockIdx.x;
    const int t = threadIdx.x;
    if (bid < PREP_SPAN_BLKS) {
        const int gw = bid * 8 + (t >> 5);   // global warp id < 28416
        const int lane = t & 31;
        const int rid = gw / 3;
        const int part = gw - rid * 3;       // 0..2: cols [part*256, part*256+256)
        const float* src; int b, s, e;
        if (rid < NSPAN1) { src = t1; b = rid >> 7; s = s1s[rid]; e = s1e[rid]; }
        else { int j = rid - NSPAN1; src = know; b = j / KN; s = sks[j]; e = ske[j]; }
        int len = e - s; if (len < 1) len = 1;
        const float inv = 1.0f / (float)len;
        const int c0 = part * 256 + lane * 8;
        const float* base = src + (size_t)(b * LSEQ + s) * DDIM + c0;
        // all 4 row loads issued upfront; rows >= len clamp to len-1 (L1 hit)
        const float* rp[4];
        float wt[4];
        #pragma unroll
        for (int rr = 0; rr < 4; rr++) {
            int cr = rr < len ? rr : len - 1;
            rp[rr] = base + (size_t)cr * DDIM;
            wt[rr] = (rr < len) ? inv : 0.0f;
        }
        float4 f[8];
        #pragma unroll
        for (int rr = 0; rr < 4; rr++) {
            f[2 * rr]     = *(const float4*)(rp[rr]);
            f[2 * rr + 1] = *(const float4*)(rp[rr] + 4);
        }
        float v[8];
        #pragma unroll
        for (int j = 0; j < 8; j++) v[j] = 0.0f;
        #pragma unroll
        for (int rr = 0; rr < 4; rr++) {
            v[0] += wt[rr] * f[2*rr].x;   v[1] += wt[rr] * f[2*rr].y;
            v[2] += wt[rr] * f[2*rr].z;   v[3] += wt[rr] * f[2*rr].w;
            v[4] += wt[rr] * f[2*rr+1].x; v[5] += wt[rr] * f[2*rr+1].y;
            v[6] += wt[rr] * f[2*rr+1].z; v[7] += wt[rr] * f[2*rr+1].w;
        }
        union { unsigned short u[8]; uint4 q; } ph;
        #pragma unroll
        for (int j = 0; j < 8; j++) {
            __half h = __float2half_rn(v[j]);
            ph.u[j] = *(unsigned short*)&h;
        }
        const int tile = rid >> 5, r = rid & 31;
        const int chunk = c0 >> 6, grp = (c0 >> 3) & 7;
        size_t off = (size_t)(tile * NCHUNK + chunk) * A_CHUNK_BYTES
                   + r * 128 + grp * 16;
        *(uint4*)(g_Ahi + off) = ph.q;
    } else if (bid < PREP_SPAN_BLKS + PREP_W_BLKS) {
        const int u = (bid - PREP_SPAN_BLKS) * 256 + t;   // [0, 30720)
        const int row = u / 96;
        const int idx8 = u - row * 96;
        const int c0 = idx8 * 8;
        union { unsigned short s[8]; uint4 q; } ph;
        if (row < OUTD) {
            const float4* p4 = (const float4*)(W + (size_t)row * DDIM + c0);
            float4 a = p4[0], bb = p4[1];
            float v[8] = {a.x, a.y, a.z, a.w, bb.x, bb.y, bb.z, bb.w};
            #pragma unroll
            for (int j = 0; j < 8; j++) {
                __half h = __float2half_rn(v[j]);
                ph.s[j] = *(unsigned short*)&h;
            }
        } else {
            ph.q = make_uint4(0, 0, 0, 0);
        }
        const int chunk = idx8 >> 3, grp = idx8 & 7;
        size_t off = (size_t)chunk * B_CHUNK_BYTES + row * 128 + grp * 16;
        *(uint4*)(g_Bhi + off) = ph.q;
    } else {
        __shared__ int f_weird, f_odd;
        if (t == 0) { f_weird = 0; f_odd = 0; }
        __syncthreads();
        int lw = 0, lo = 0;
        for (int i = t; i < NB * KN; i += 256) {
            unsigned char vv = maskk[i];
            if (vv > 1) lw = 1;
            if (vv && (i & 3)) lo = 1;
        }
        for (int i = t; i < NB * L1; i += 256) {
            unsigned char vv = mask1[i];
            if (vv > 1) lw = 1;
            if (vv && (i & 3)) lo = 1;
        }
        if (lw) atomicOr(&f_weird, 1);
        if (lo) atomicOr(&f_odd, 1);
        __syncthreads();
        if (t == 0) g_mask_mode = f_weird ? 2 : (f_odd ? 0 : 1);
    }
}

// ---------------------------------------------------------------------------
// GEMM: fp16 1-sweep, M=32 x N=320 x K=768 per CTA, 296 CTAs x 256 threads,
// 2 CTAs/SM. Warp w covers cols [w*40, w*40+40). Fused bias+LN+score epilogue.
// ---------------------------------------------------------------------------
__global__ __launch_bounds__(256, 2)
void gemm_kernel(const float* __restrict__ b_lin, const float* __restrict__ gamma,
                 const float* __restrict__ beta, const float* __restrict__ w_score,
                 const float* __restrict__ b_score, float* __restrict__ out) {
    extern __shared__ char smem[];
    const uint32_t sbase = smem_u32(smem);
    const int t = threadIdx.x;
    const int blk = blockIdx.x;
    const int w = t >> 5, lane = t & 31;
    const int nb0 = w * 40;

    float* tb = (float*)(smem + SM_TAB);
    for (int i = t; i < NPADB; i += 256) {
        tb[i]             = (i < OUTD) ? b_lin[i]   : 0.0f;
        tb[NPADB + i]     = (i < OUTD) ? gamma[i]   : 0.0f;
        tb[2 * NPADB + i] = (i < OUTD) ? beta[i]    : 0.0f;
        tb[3 * NPADB + i] = (i < OUTD) ? w_score[i] : 0.0f;
    }

    float acc[2][5][4];
    #pragma unroll
    for (int mf = 0; mf < 2; mf++)
        #pragma unroll
        for (int nf = 0; nf < 5; nf++)
            #pragma unroll
            for (int q = 0; q < 4; q++) acc[mf][nf][q] = 0.0f;

    const unsigned char* atile = g_Ahi + (size_t)blk * NCHUNK * A_CHUNK_BYTES;

    {
        const uint32_t sb = sbase;
        {
            int idx = t;
            int row = idx >> 3, u = idx & 7;
            uint32_t d = row * 128 + ((u ^ (row & 7)) << 4);
            cp16(sb + OFF_AHI + d, atile + idx * 16);
        }
        #pragma unroll
        for (int j = 0; j < 10; j++) {
            int idx = t + 256 * j;
            int row = idx >> 3, u = idx & 7;
            uint32_t d = row * 128 + ((u ^ (row & 7)) << 4);
            cp16(sb + OFF_BHI + d, g_Bhi + idx * 16);
        }
        asm volatile("cp.async.commit_group;" ::: "memory");
    }

    #pragma unroll 1
    for (int c = 0; c < NCHUNK; ++c) {
        if (c + 1 < NCHUNK) {
            const uint32_t sb2 = sbase + ((c + 1) & 1) * STAGE_BYTES;
            const unsigned char* ah = atile + (size_t)(c + 1) * A_CHUNK_BYTES;
            const unsigned char* bh = g_Bhi + (size_t)(c + 1) * B_CHUNK_BYTES;
            {
                int idx = t;
                int row = idx >> 3, u = idx & 7;
                uint32_t d = row * 128 + ((u ^ (row & 7)) << 4);
                cp16(sb2 + OFF_AHI + d, ah + idx * 16);
            }
            #pragma unroll
            for (int j = 0; j < 10; j++) {
                int idx = t + 256 * j;
                int row = idx >> 3, u = idx & 7;
                uint32_t d = row * 128 + ((u ^ (row & 7)) << 4);
                cp16(sb2 + OFF_BHI + d, bh + idx * 16);
            }
            asm volatile("cp.async.commit_group;" ::: "memory");
            asm volatile("cp.async.wait_group 1;" ::: "memory");
        } else {
            asm volatile("cp.async.wait_group 0;" ::: "memory");
        }
        __syncthreads();

        const uint32_t sb = sbase + (c & 1) * STAGE_BYTES;
        const int sub = lane >> 3, rin = lane & 7;
        #pragma unroll
        for (int ks = 0; ks < 4; ks++) {
            uint32_t ah[2][4];
            #pragma unroll
            for (int mf = 0; mf < 2; mf++) {
                int row = mf * 16 + rin + ((sub & 1) << 3);
                int u = ks * 2 + (sub >> 1);
                ldsm4(ah[mf], swz_addr(sb + OFF_AHI, row, u));
            }
            #pragma unroll
            for (int nf = 0; nf < 5; nf++) {
                int brow = nb0 + nf * 8 + rin;
                int bu = ks * 2 + (sub & 1);
                uint32_t bh[2];
                ldsm2(bh, swz_addr(sb + OFF_BHI, brow, bu));
                mma16816(acc[0][nf], ah[0], bh);
                mma16816(acc[1][nf], ah[1], bh);
            }
        }
        __syncthreads();
    }

    // ---- epilogue: bias + LayerNorm + h write + score ----
    float* red_sum  = (float*)(smem + SM_RED);   // [8][32]
    float* red_sq   = red_sum + 256;             // [8][32]
    float* red_sc   = red_sum + 512;             // [8][32]
    float* red_mean = red_sum + 768;             // [32]
    float* red_rstd = red_sum + 800;             // [32]

    float sum[4] = {0, 0, 0, 0}, sq[4] = {0, 0, 0, 0};
    #pragma unroll
    for (int mf = 0; mf < 2; mf++)
        #pragma unroll
        for (int nf = 0; nf < 5; nf++) {
            int c0 = nb0 + nf * 8 + 2 * (lane & 3);
            float v0 = acc[mf][nf][0] + tb[c0];
            float v1 = acc[mf][nf][1] + tb[c0 + 1];
            float v2 = acc[mf][nf][2] + tb[c0];
            float v3 = acc[mf][nf][3] + tb[c0 + 1];
            sum[mf * 2]     += v0 + v1;  sq[mf * 2]     += v0 * v0 + v1 * v1;
            sum[mf * 2 + 1] += v2 + v3;  sq[mf * 2 + 1] += v2 * v2 + v3 * v3;
        }
    #pragma unroll
    for (int ri = 0; ri < 4; ri++) {
        #pragma unroll
        for (int o = 1; o <= 2; o <<= 1) {
            sum[ri] += __shfl_xor_sync(0xffffffffu, sum[ri], o);
            sq[ri]  += __shfl_xor_sync(0xffffffffu, sq[ri], o);
        }
    }
    if ((lane & 3) == 0) {
        #pragma unroll
        for (int ri = 0; ri < 4; ri++) {
            int row = (ri >> 1) * 16 + (ri & 1) * 8 + (lane >> 2);
            red_sum[w * 32 + row] = sum[ri];
            red_sq[w * 32 + row]  = sq[ri];
        }
    }
    __syncthreads();
    if (t < TROWS) {
        float s = 0.0f, qv = 0.0f;
        #pragma unroll
        for (int j = 0; j < 8; j++) { s += red_sum[j * 32 + t]; qv += red_sq[j * 32 + t]; }
        float mean = s * (1.0f / OUTD);
        float var = qv * (1.0f / OUTD) - mean * mean;
        red_mean[t] = mean;
        red_rstd[t] = rsqrtf(fmaxf(var, 0.0f) + EPSV);
    }
    __syncthreads();

    const float* sg  = tb + NPADB;
    const float* sbe = tb + 2 * NPADB;
    const float* sw  = tb + 3 * NPADB;
    float sc[4] = {0, 0, 0, 0};
    #pragma unroll
    for (int mf = 0; mf < 2; mf++) {
        int row01 = mf * 16 + (lane >> 2);
        int row23 = row01 + 8;
        float m0 = red_mean[row01], r0 = red_rstd[row01];
        float m1 = red_mean[row23], r1 = red_rstd[row23];
        int g01 = blk * TROWS + row01;
        int g23 = blk * TROWS + row23;
        float* o01 = (blk < NBLK1T) ? out + (size_t)g01 * OUTD
                                    : out + HK_OFF + (size_t)(g01 - NSPAN1) * OUTD;
        float* o23 = (blk < NBLK1T) ? out + (size_t)g23 * OUTD
                                    : out + HK_OFF + (size_t)(g23 - NSPAN1) * OUTD;
        #pragma unroll
        for (int nf = 0; nf < 5; nf++) {
            int c0 = nb0 + nf * 8 + 2 * (lane & 3);
            float v0 = acc[mf][nf][0] + tb[c0];
            float v1 = acc[mf][nf][1] + tb[c0 + 1];
            float v2 = acc[mf][nf][2] + tb[c0];
            float v3 = acc[mf][nf][3] + tb[c0 + 1];
            float h0 = (v0 - m0) * r0 * sg[c0]     + sbe[c0];
            float h1 = (v1 - m0) * r0 * sg[c0 + 1] + sbe[c0 + 1];
            float h2 = (v2 - m1) * r1 * sg[c0]     + sbe[c0];
            float h3 = (v3 - m1) * r1 * sg[c0 + 1] + sbe[c0 + 1];
            sc[mf * 2]     += h0 * sw[c0] + h1 * sw[c0 + 1];
            sc[mf * 2 + 1] += h2 * sw[c0] + h3 * sw[c0 + 1];
            if (c0 < OUTD) {
                *(float2*)(o01 + c0) = make_float2(h0, h1);
                *(float2*)(o23 + c0) = make_float2(h2, h3);
            }
        }
    }
    #pragma unroll
    for (int ri = 0; ri < 4; ri++)
        #pragma unroll
        for (int o = 1; o <= 2; o <<= 1)
            sc[ri] += __shfl_xor_sync(0xffffffffu, sc[ri], o);
    if ((lane & 3) == 0) {
        #pragma unroll
        for (int ri = 0; ri < 4; ri++) {
            int row = (ri >> 1) * 16 + (ri & 1) * 8 + (lane >> 2);
            red_sc[w * 32 + row] = sc[ri];
        }
    }
    __syncthreads();
    if (t < TROWS) {
        float s = 0.0f;
        #pragma unroll
        for (int j = 0; j < 8; j++) s += red_sc[j * 32 + t];
        g_scores[blk * TROWS + t] = s + b_score[0];
    }
}

// ---------------------------------------------------------------------------
// softmax + broadcast: blocks 0..127 = (batch, half); 128..191 know softmax.
// ---------------------------------------------------------------------------
__global__ __launch_bounds__(256)
void softmax_bcast_kernel(const void* __restrict__ mask1,
                          const void* __restrict__ maskk,
                          float* __restrict__ out) {
    const int mode = g_mask_mode;
    const int t = threadIdx.x;
    if (blockIdx.x < 2 * NB) {
        const int b = blockIdx.x >> 1;
        const int half = blockIdx.x & 1;
        __shared__ float red[4];
        __shared__ float sh[L1];
        float scv = 0.0f; bool msk = true;
        if (t < L1) {
            scv = g_scores[b * L1 + t];
            msk = read_mask(mask1, b * L1 + t, mode);
        }
        float val = (t < L1 && !msk) ? scv : -3.0e38f;
        float mx = val;
        #pragma unroll
        for (int o = 16; o; o >>= 1) mx = fmaxf(mx, __shfl_xor_sync(0xffffffffu, mx, o));
        if (t < L1 && (t & 31) == 0) red[t >> 5] = mx;
        __syncthreads();
        mx = fmaxf(fmaxf(red[0], red[1]), fmaxf(red[2], red[3]));
        __syncthreads();
        float ex = (t < L1 && !msk) ? expf(scv - mx) : 0.0f;
        float sm = ex;
        #pragma unroll
        for (int o = 16; o; o >>= 1) sm += __shfl_xor_sync(0xffffffffu, sm, o);
        if (t < L1 && (t & 31) == 0) red[t >> 5] = sm;
        __syncthreads();
        sm = red[0] + red[1] + red[2] + red[3];
        if (t < L1) sh[t] = ex / sm;
        __syncthreads();
        float4* o4 = (float4*)(out + SCORE_OFF + (size_t)b * L1 * OUTD);
        const int Q = OUTD / 4;            // 75
        for (int w2 = t; w2 < 64 * Q; w2 += 256) {
            int row = half * 64 + w2 / Q;
            float p = sh[row];
            o4[row * Q + (w2 % Q)] = make_float4(p, p, p, p);
        }
    } else {
        const int b = blockIdx.x - 2 * NB;
        if (t < 32) {
            bool msk = true;
            float scv = 0.0f;
            if (t < KN) {
                msk = read_mask(maskk, b * KN + t, mode);
                scv = g_scores[NSPAN1 + b * KN + t];
            }
            float val = (t < KN && !msk) ? scv : -3.0e38f;
            float mx = val;
            #pragma unroll
            for (int o = 16; o; o >>= 1) mx = fmaxf(mx, __shfl_xor_sync(0xffffffffu, mx, o));
            float ex = (t < KN && !msk) ? expf(scv - mx) : 0.0f;
            float sm = ex;
            #pragma unroll
            for (int o = 16; o; o >>= 1) sm += __shfl_xor_sync(0xffffffffu, sm, o);
            if (t < KN) out[SK_OFF + b * KN + t] = ex / sm;
        }
    }
}

extern "C" void kernel_launch(void* const* d_in, const int* in_sizes, int n_in,
                              void* d_out, int out_size) {
    const float* t1    = (const float*)d_in[0];
    const float* know  = (const float*)d_in[1];
    const int*   s1s   = (const int*)d_in[2];
    const int*   s1e   = (const int*)d_in[3];
    const void*  mask1 = d_in[4];
    const int*   sks   = (const int*)d_in[5];
    const int*   ske   = (const int*)d_in[6];
    const void*  maskk = d_in[7];
    const float* W     = (const float*)d_in[8];
    const float* bl    = (const float*)d_in[9];
    const float* gm    = (const float*)d_in[10];
    const float* bt    = (const float*)d_in[11];
    const float* ws    = (const float*)d_in[12];
    const float* bs    = (const float*)d_in[13];
    float* out = (float*)d_out;

    cudaFuncSetAttribute(gemm_kernel, cudaFuncAttributeMaxDynamicSharedMemorySize,
                         SMEM_BYTES);
    prep_kernel<<<PREP_BLKS, 256>>>(t1, know, s1s, s1e, sks, ske, W,
                                    (const unsigned char*)mask1,
                                    (const unsigned char*)maskk);
    gemm_kernel<<<NTILES, 256, SMEM_BYTES>>>(bl, gm, bt, ws, bs, out);
    softmax_bcast_kernel<<<3 * NB, 256>>>(mask1, maskk, out);
}

// round 12
// speedup vs baseline: 1.0537x; 1.0537x over previous
#include <cuda_runtime.h>
#include <cuda_fp16.h>
#include <stdint.h>
#include <math.h>

#define NB   64
#define LSEQ 510
#define DDIM 768
#define L1   128
#define KN   20
#define OUTD 300
#define EPSV 1e-5f

#define NSPAN1 (NB * L1)          // 8192
#define NSPANK (NB * KN)          // 1280
#define NSPANS (NSPAN1 + NSPANK)  // 9472
#define TROWS  32
#define NTILES (NSPANS / TROWS)   // 296 = 2 CTAs x 148 SMs
#define NBLK1T (NSPAN1 / TROWS)   // 256

#define NCHUNK 12                 // K chunks of 64
#define NPADB  320

#define H1_OFF    0
#define SCORE_OFF (NB * L1 * OUTD)
#define HK_OFF    (2 * NB * L1 * OUTD)
#define SK_OFF    (HK_OFF + NB * KN * OUTD)

#define B_CHUNK_BYTES 40960        // 320 rows x 128B (fp16)

__device__ __align__(16) unsigned char g_Bhi[NCHUNK * B_CHUNK_BYTES];
__device__ float g_scores[NSPANS];
__device__ int   g_mask_mode;

// smem: per stage A 4K | B 40K = 44K; x2 stages; tables; reduction
#define STAGE_BYTES 45056
#define OFF_AHI 0
#define OFF_BHI 4096
#define SM_TAB  (2 * STAGE_BYTES)          // 90112
#define SM_RED  (SM_TAB + 5120)           // 95232
#define SMEM_BYTES (SM_RED + 3584)        // 98816 -> 2 CTAs/SM

static __device__ __forceinline__ uint32_t smem_u32(const void* p) {
    uint32_t a;
    asm("{ .reg .u64 t; cvta.to.shared.u64 t, %1; cvt.u32.u64 %0, t; }" : "=r"(a) : "l"(p));
    return a;
}
static __device__ __forceinline__ void cp16(uint32_t s, const void* g) {
    asm volatile("cp.async.cg.shared.global [%0], [%1], 16;" :: "r"(s), "l"(g) : "memory");
}
static __device__ __forceinline__ void ldsm4(uint32_t* r, uint32_t addr) {
    asm volatile("ldmatrix.sync.aligned.m8n8.x4.shared.b16 {%0,%1,%2,%3}, [%4];"
                 : "=r"(r[0]), "=r"(r[1]), "=r"(r[2]), "=r"(r[3]) : "r"(addr));
}
static __device__ __forceinline__ void ldsm2(uint32_t* r, uint32_t addr) {
    asm volatile("ldmatrix.sync.aligned.m8n8.x2.shared.b16 {%0,%1}, [%2];"
                 : "=r"(r[0]), "=r"(r[1]) : "r"(addr));
}
static __device__ __forceinline__ void mma16816(float* c, const uint32_t* a,
                                                const uint32_t* b) {
    asm volatile(
        "mma.sync.aligned.m16n8k16.row.col.f32.f16.f16.f32 "
        "{%0,%1,%2,%3}, {%4,%5,%6,%7}, {%8,%9}, {%0,%1,%2,%3};"
        : "+f"(c[0]), "+f"(c[1]), "+f"(c[2]), "+f"(c[3])
        : "r"(a[0]), "r"(a[1]), "r"(a[2]), "r"(a[3]), "r"(b[0]), "r"(b[1]));
}
static __device__ __forceinline__ uint32_t swz_addr(uint32_t base, int row, int u) {
    return base + row * 128 + ((u ^ (row & 7)) << 4);
}
static __device__ __forceinline__ bool read_mask(const void* m, int i, int mode) {
    if (mode == 0) return ((const unsigned char*)m)[i] != 0;
    if (mode == 1) return ((const int*)m)[i] != 0;
    return ((const float*)m)[i] != 0.0f;
}

// ---------------------------------------------------------------------------
// prep_small: blocks [0,120): W -> fp16 swizzled scratch; block 120: mask.
// ---------------------------------------------------------------------------
__global__ __launch_bounds__(256)
void prep_small_kernel(const float* __restrict__ W,
                       const unsigned char* __restrict__ mask1,
                       const unsigned char* __restrict__ maskk) {
    const int bid = blockIdx.x;
    const int t = threadIdx.x;
    if (bid < 120) {
        const int u = bid * 256 + t;                // [0, 30720)
        const int row = u / 96;
        const int idx8 = u - row * 96;
        const int c0 = idx8 * 8;
        union { unsigned short s[8]; uint4 q; } ph;
        if (row < OUTD) {
            const float4* p4 = (const float4*)(W + (size_t)row * DDIM + c0);
            float4 a = p4[0], bb = p4[1];
            float v[8] = {a.x, a.y, a.z, a.w, bb.x, bb.y, bb.z, bb.w};
            #pragma unroll
            for (int j = 0; j < 8; j++) {
                __half h = __float2half_rn(v[j]);
                ph.s[j] = *(unsigned short*)&h;
            }
        } else {
            ph.q = make_uint4(0, 0, 0, 0);
        }
        const int chunk = idx8 >> 3, grp = idx8 & 7;
        size_t off = (size_t)chunk * B_CHUNK_BYTES + row * 128 + grp * 16;
        *(uint4*)(g_Bhi + off) = ph.q;
    } else {
        __shared__ int f_weird, f_odd;
        if (t == 0) { f_weird = 0; f_odd = 0; }
        __syncthreads();
        int lw = 0, lo = 0;
        for (int i = t; i < NB * KN; i += 256) {
            unsigned char vv = maskk[i];
            if (vv > 1) lw = 1;
            if (vv && (i & 3)) lo = 1;
        }
        for (int i = t; i < NB * L1; i += 256) {
            unsigned char vv = mask1[i];
            if (vv > 1) lw = 1;
            if (vv && (i & 3)) lo = 1;
        }
        if (lw) atomicOr(&f_weird, 1);
        if (lo) atomicOr(&f_odd, 1);
        __syncthreads();
        if (t == 0) g_mask_mode = f_weird ? 2 : (f_odd ? 0 : 1);
    }
}

// ---------------------------------------------------------------------------
// GEMM with fused span pooling: M=32 x N=320 x K=768 per CTA, 296 CTAs x 256,
// 2 CTAs/SM. Thread t pools row (t>>3), cols [(t&7)*8 .. +8) of each chunk
// (4 clamped row-reads, weighted FMA) -> fp16 -> swizzled smem A stage.
// B double-buffered via cp.async from fp16 scratch. Fused bias+LN+score.
// ---------------------------------------------------------------------------
__global__ __launch_bounds__(256, 2)
void gemm_kernel(const float* __restrict__ t1, const float* __restrict__ know,
                 const int* __restrict__ s1s, const int* __restrict__ s1e,
                 const int* __restrict__ sks, const int* __restrict__ ske,
                 const float* __restrict__ b_lin, const float* __restrict__ gamma,
                 const float* __restrict__ beta, const float* __restrict__ w_score,
                 const float* __restrict__ b_score, float* __restrict__ out) {
    extern __shared__ char smem[];
    const uint32_t sbase = smem_u32(smem);
    const int t = threadIdx.x;
    const int blk = blockIdx.x;
    const int w = t >> 5, lane = t & 31;
    const int nb0 = w * 40;

    float* tb = (float*)(smem + SM_TAB);
    for (int i = t; i < NPADB; i += 256) {
        tb[i]             = (i < OUTD) ? b_lin[i]   : 0.0f;
        tb[NPADB + i]     = (i < OUTD) ? gamma[i]   : 0.0f;
        tb[2 * NPADB + i] = (i < OUTD) ? beta[i]    : 0.0f;
        tb[3 * NPADB + i] = (i < OUTD) ? w_score[i] : 0.0f;
    }

    // ---- span metadata for pooled row r = t>>3 ----
    const int r = t >> 3, grp = t & 7;
    const int rid = blk * TROWS + r;
    const float* rp[4];
    float wt[4];
    {
        const float* src; int b, s, e;
        if (rid < NSPAN1) { src = t1; b = rid >> 7; s = s1s[rid]; e = s1e[rid]; }
        else { int j = rid - NSPAN1; src = know; b = j / KN; s = sks[j]; e = ske[j]; }
        int len = e - s; if (len < 1) len = 1;
        const float inv = 1.0f / (float)len;
        const float* base = src + (size_t)(b * LSEQ + s) * DDIM + grp * 8;
        #pragma unroll
        for (int rr = 0; rr < 4; rr++) {
            int cr = rr < len ? rr : len - 1;
            rp[rr] = base + (size_t)cr * DDIM;
            wt[rr] = (rr < len) ? inv : 0.0f;
        }
    }

    float acc[2][5][4];
    #pragma unroll
    for (int mf = 0; mf < 2; mf++)
        #pragma unroll
        for (int nf = 0; nf < 5; nf++)
            #pragma unroll
            for (int q = 0; q < 4; q++) acc[mf][nf][q] = 0.0f;

    // ---- pool chunk 0 into v ----
    float v[8];
    {
        float4 f[8];
        #pragma unroll
        for (int rr = 0; rr < 4; rr++) {
            f[2 * rr]     = *(const float4*)(rp[rr]);
            f[2 * rr + 1] = *(const float4*)(rp[rr] + 4);
        }
        #pragma unroll
        for (int j = 0; j < 8; j++) v[j] = 0.0f;
        #pragma unroll
        for (int rr = 0; rr < 4; rr++) {
            v[0] += wt[rr] * f[2*rr].x;   v[1] += wt[rr] * f[2*rr].y;
            v[2] += wt[rr] * f[2*rr].z;   v[3] += wt[rr] * f[2*rr].w;
            v[4] += wt[rr] * f[2*rr+1].x; v[5] += wt[rr] * f[2*rr+1].y;
            v[6] += wt[rr] * f[2*rr+1].z; v[7] += wt[rr] * f[2*rr+1].w;
        }
    }
    // ---- issue B chunk 0 ----
    #pragma unroll
    for (int j = 0; j < 10; j++) {
        int idx = t + 256 * j;
        int row = idx >> 3, u = idx & 7;
        uint32_t d = row * 128 + ((u ^ (row & 7)) << 4);
        cp16(sbase + OFF_BHI + d, g_Bhi + idx * 16);
    }
    asm volatile("cp.async.commit_group;" ::: "memory");

    #pragma unroll 1
    for (int c = 0; c < NCHUNK; ++c) {
        const uint32_t sb = sbase + (c & 1) * STAGE_BYTES;
        // store pooled A(c) into this stage (fp16, swizzled)
        {
            union { unsigned short u[8]; uint4 q; } ph;
            #pragma unroll
            for (int j = 0; j < 8; j++) {
                __half h = __float2half_rn(v[j]);
                ph.u[j] = *(unsigned short*)&h;
            }
            *(uint4*)(smem + (c & 1) * STAGE_BYTES + OFF_AHI
                      + r * 128 + ((grp ^ (r & 7)) << 4)) = ph.q;
        }
        if (c + 1 < NCHUNK) {
            const uint32_t sb2 = sbase + ((c + 1) & 1) * STAGE_BYTES;
            const unsigned char* bh = g_Bhi + (size_t)(c + 1) * B_CHUNK_BYTES;
            #pragma unroll
            for (int j = 0; j < 10; j++) {
                int idx = t + 256 * j;
                int row = idx >> 3, u = idx & 7;
                uint32_t d = row * 128 + ((u ^ (row & 7)) << 4);
                cp16(sb2 + OFF_BHI + d, bh + idx * 16);
            }
            asm volatile("cp.async.commit_group;" ::: "memory");
            asm volatile("cp.async.wait_group 1;" ::: "memory");
        } else {
            asm volatile("cp.async.wait_group 0;" ::: "memory");
        }
        __syncthreads();

        // MMA(c)
        {
            const int sub = lane >> 3, rin = lane & 7;
            #pragma unroll
            for (int ks = 0; ks < 4; ks++) {
                uint32_t ah[2][4];
                #pragma unroll
                for (int mf = 0; mf < 2; mf++) {
                    int row = mf * 16 + rin + ((sub & 1) << 3);
                    int u = ks * 2 + (sub >> 1);
                    ldsm4(ah[mf], swz_addr(sb + OFF_AHI, row, u));
                }
                #pragma unroll
                for (int nf = 0; nf < 5; nf++) {
                    int brow = nb0 + nf * 8 + rin;
                    int bu = ks * 2 + (sub & 1);
                    uint32_t bh[2];
                    ldsm2(bh, swz_addr(sb + OFF_BHI, brow, bu));
                    mma16816(acc[0][nf], ah[0], bh);
                    mma16816(acc[1][nf], ah[1], bh);
                }
            }
        }
        // pool chunk c+1 (hidden under other CTA/warp MMA work)
        if (c + 1 < NCHUNK) {
            const int c0 = (c + 1) * 64;
            float4 f[8];
            #pragma unroll
            for (int rr = 0; rr < 4; rr++) {
                f[2 * rr]     = *(const float4*)(rp[rr] + c0);
                f[2 * rr + 1] = *(const float4*)(rp[rr] + c0 + 4);
            }
            #pragma unroll
            for (int j = 0; j < 8; j++) v[j] = 0.0f;
            #pragma unroll
            for (int rr = 0; rr < 4; rr++) {
                v[0] += wt[rr] * f[2*rr].x;   v[1] += wt[rr] * f[2*rr].y;
                v[2] += wt[rr] * f[2*rr].z;   v[3] += wt[rr] * f[2*rr].w;
                v[4] += wt[rr] * f[2*rr+1].x; v[5] += wt[rr] * f[2*rr+1].y;
                v[6] += wt[rr] * f[2*rr+1].z; v[7] += wt[rr] * f[2*rr+1].w;
            }
        }
        __syncthreads();
    }

    // ---- epilogue: bias + LayerNorm + h write + score ----
    float* red_sum  = (float*)(smem + SM_RED);   // [8][32]
    float* red_sq   = red_sum + 256;             // [8][32]
    float* red_sc   = red_sum + 512;             // [8][32]
    float* red_mean = red_sum + 768;             // [32]
    float* red_rstd = red_sum + 800;             // [32]

    float sum[4] = {0, 0, 0, 0}, sq[4] = {0, 0, 0, 0};
    #pragma unroll
    for (int mf = 0; mf < 2; mf++)
        #pragma unroll
        for (int nf = 0; nf < 5; nf++) {
            int c0 = nb0 + nf * 8 + 2 * (lane & 3);
            float v0 = acc[mf][nf][0] + tb[c0];
            float v1 = acc[mf][nf][1] + tb[c0 + 1];
            float v2 = acc[mf][nf][2] + tb[c0];
            float v3 = acc[mf][nf][3] + tb[c0 + 1];
            sum[mf * 2]     += v0 + v1;  sq[mf * 2]     += v0 * v0 + v1 * v1;
            sum[mf * 2 + 1] += v2 + v3;  sq[mf * 2 + 1] += v2 * v2 + v3 * v3;
        }
    #pragma unroll
    for (int ri = 0; ri < 4; ri++) {
        #pragma unroll
        for (int o = 1; o <= 2; o <<= 1) {
            sum[ri] += __shfl_xor_sync(0xffffffffu, sum[ri], o);
            sq[ri]  += __shfl_xor_sync(0xffffffffu, sq[ri], o);
        }
    }
    if ((lane & 3) == 0) {
        #pragma unroll
        for (int ri = 0; ri < 4; ri++) {
            int row = (ri >> 1) * 16 + (ri & 1) * 8 + (lane >> 2);
            red_sum[w * 32 + row] = sum[ri];
            red_sq[w * 32 + row]  = sq[ri];
        }
    }
    __syncthreads();
    if (t < TROWS) {
        float s = 0.0f, qv = 0.0f;
        #pragma unroll
        for (int j = 0; j < 8; j++) { s += red_sum[j * 32 + t]; qv += red_sq[j * 32 + t]; }
        float mean = s * (1.0f / OUTD);
        float var = qv * (1.0f / OUTD) - mean * mean;
        red_mean[t] = mean;
        red_rstd[t] = rsqrtf(fmaxf(var, 0.0f) + EPSV);
    }
    __syncthreads();

    const float* sg  = tb + NPADB;
    const float* sbe = tb + 2 * NPADB;
    const float* sw  = tb + 3 * NPADB;
    float sc[4] = {0, 0, 0, 0};
    #pragma unroll
    for (int mf = 0; mf < 2; mf++) {
        int row01 = mf * 16 + (lane >> 2);
        int row23 = row01 + 8;
        float m0 = red_mean[row01], r0 = red_rstd[row01];
        float m1 = red_mean[row23], r1 = red_rstd[row23];
        int g01 = blk * TROWS + row01;
        int g23 = blk * TROWS + row23;
        float* o01 = (blk < NBLK1T) ? out + (size_t)g01 * OUTD
                                    : out + HK_OFF + (size_t)(g01 - NSPAN1) * OUTD;
        float* o23 = (blk < NBLK1T) ? out + (size_t)g23 * OUTD
                                    : out + HK_OFF + (size_t)(g23 - NSPAN1) * OUTD;
        #pragma unroll
        for (int nf = 0; nf < 5; nf++) {
            int c0 = nb0 + nf * 8 + 2 * (lane & 3);
            float v0 = acc[mf][nf][0] + tb[c0];
            float v1 = acc[mf][nf][1] + tb[c0 + 1];
            float v2 = acc[mf][nf][2] + tb[c0];
            float v3 = acc[mf][nf][3] + tb[c0 + 1];
            float h0 = (v0 - m0) * r0 * sg[c0]     + sbe[c0];
            float h1 = (v1 - m0) * r0 * sg[c0 + 1] + sbe[c0 + 1];
            float h2 = (v2 - m1) * r1 * sg[c0]     + sbe[c0];
            float h3 = (v3 - m1) * r1 * sg[c0 + 1] + sbe[c0 + 1];
            sc[mf * 2]     += h0 * sw[c0] + h1 * sw[c0 + 1];
            sc[mf * 2 + 1] += h2 * sw[c0] + h3 * sw[c0 + 1];
            if (c0 < OUTD) {
                *(float2*)(o01 + c0) = make_float2(h0, h1);
                *(float2*)(o23 + c0) = make_float2(h2, h3);
            }
        }
    }
    #pragma unroll
    for (int ri = 0; ri < 4; ri++)
        #pragma unroll
        for (int o = 1; o <= 2; o <<= 1)
            sc[ri] += __shfl_xor_sync(0xffffffffu, sc[ri], o);
    if ((lane & 3) == 0) {
        #pragma unroll
        for (int ri = 0; ri < 4; ri++) {
            int row = (ri >> 1) * 16 + (ri & 1) * 8 + (lane >> 2);
            red_sc[w * 32 + row] = sc[ri];
        }
    }
    __syncthreads();
    if (t < TROWS) {
        float s = 0.0f;
        #pragma unroll
        for (int j = 0; j < 8; j++) s += red_sc[j * 32 + t];
        g_scores[blk * TROWS + t] = s + b_score[0];
    }
}

// ---------------------------------------------------------------------------
// softmax + broadcast: blocks 0..127 = (batch, half); 128..191 know softmax.
// ---------------------------------------------------------------------------
__global__ __launch_bounds__(256)
void softmax_bcast_kernel(const void* __restrict__ mask1,
                          const void* __restrict__ maskk,
                          float* __restrict__ out) {
    const int mode = g_mask_mode;
    const int t = threadIdx.x;
    if (blockIdx.x < 2 * NB) {
        const int b = blockIdx.x >> 1;
        const int half = blockIdx.x & 1;
        __shared__ float red[4];
        __shared__ float sh[L1];
        float scv = 0.0f; bool msk = true;
        if (t < L1) {
            scv = g_scores[b * L1 + t];
            msk = read_mask(mask1, b * L1 + t, mode);
        }
        float val = (t < L1 && !msk) ? scv : -3.0e38f;
        float mx = val;
        #pragma unroll
        for (int o = 16; o; o >>= 1) mx = fmaxf(mx, __shfl_xor_sync(0xffffffffu, mx, o));
        if (t < L1 && (t & 31) == 0) red[t >> 5] = mx;
        __syncthreads();
        mx = fmaxf(fmaxf(red[0], red[1]), fmaxf(red[2], red[3]));
        __syncthreads();
        float ex = (t < L1 && !msk) ? expf(scv - mx) : 0.0f;
        float sm = ex;
        #pragma unroll
        for (int o = 16; o; o >>= 1) sm += __shfl_xor_sync(0xffffffffu, sm, o);
        if (t < L1 && (t & 31) == 0) red[t >> 5] = sm;
        __syncthreads();
        sm = red[0] + red[1] + red[2] + red[3];
        if (t < L1) sh[t] = ex / sm;
        __syncthreads();
        float4* o4 = (float4*)(out + SCORE_OFF + (size_t)b * L1 * OUTD);
        const int Q = OUTD / 4;            // 75
        for (int w2 = t; w2 < 64 * Q; w2 += 256) {
            int row = half * 64 + w2 / Q;
            float p = sh[row];
            o4[row * Q + (w2 % Q)] = make_float4(p, p, p, p);
        }
    } else {
        const int b = blockIdx.x - 2 * NB;
        if (t < 32) {
            bool msk = true;
            float scv = 0.0f;
            if (t < KN) {
                msk = read_mask(maskk, b * KN + t, mode);
                scv = g_scores[NSPAN1 + b * KN + t];
            }
            float val = (t < KN && !msk) ? scv : -3.0e38f;
            float mx = val;
            #pragma unroll
            for (int o = 16; o; o >>= 1) mx = fmaxf(mx, __shfl_xor_sync(0xffffffffu, mx, o));
            float ex = (t < KN && !msk) ? expf(scv - mx) : 0.0f;
            float sm = ex;
            #pragma unroll
            for (int o = 16; o; o >>= 1) sm += __shfl_xor_sync(0xffffffffu, sm, o);
            if (t < KN) out[SK_OFF + b * KN + t] = ex / sm;
        }
    }
}

extern "C" void kernel_launch(void* const* d_in, const int* in_sizes, int n_in,
                              void* d_out, int out_size) {
    const float* t1    = (const float*)d_in[0];
    const float* know  = (const float*)d_in[1];
    const int*   s1s   = (const int*)d_in[2];
    const int*   s1e   = (const int*)d_in[3];
    const void*  mask1 = d_in[4];
    const int*   sks   = (const int*)d_in[5];
    const int*   ske   = (const int*)d_in[6];
    const void*  maskk = d_in[7];
    const float* W     = (const float*)d_in[8];
    const float* bl    = (const float*)d_in[9];
    const float* gm    = (const float*)d_in[10];
    const float* bt    = (const float*)d_in[11];
    const float* ws    = (const float*)d_in[12];
    const float* bs    = (const float*)d_in[13];
    float* out = (float*)d_out;

    cudaFuncSetAttribute(gemm_kernel, cudaFuncAttributeMaxDynamicSharedMemorySize,
                         SMEM_BYTES);
    prep_small_kernel<<<121, 256>>>(W, (const unsigned char*)mask1,
                                    (const unsigned char*)maskk);
    gemm_kernel<<<NTILES, 256, SMEM_BYTES>>>(t1, know, s1s, s1e, sks, ske,
                                             bl, gm, bt, ws, bs, out);
    softmax_bcast_kernel<<<3 * NB, 256>>>(mask1, maskk, out);
}